// round 7
// baseline (speedup 1.0000x reference)
#include <cuda_runtime.h>
#include <cuda_bf16.h>
#include <stdint.h>
#include <math.h>

#define NN 100000
#define NE 524288
#define EPSC 1e-5f
#define EDGE_TILES 4096
#define NODE_TILES2 391
#define GRID_P 148
#define SQRT1_2 0.70710678118654752440f

// g_T[n][0:128]=x@W1[0:128]  [128:256]=x@W1[128:256]  [256:384]=x@Wg[0:128]  [384:512]=x@Wg[128:256]
static __device__ float g_T[(size_t)NN * 512];

// Pre-split, pre-swizzled bf16 hi/lo weight images (built once by prep_kernel)
static __device__ char g_B1H_[65536], g_B1L_[65536];       // [W1e|Wge] 256n x 128k
static __device__ char g_W2H_[32768], g_W2L_[32768];       // W2 128n x 128k
static __device__ char g_BNH_[2][65536], g_BNL_[2][65536]; // node W1 / Wg, 256n x 128k

// ---------------- helpers ----------------
__device__ __forceinline__ int swb(int row, int b) {           // 256B rows, xor swizzle
    return row * 256 + (b ^ ((row & 7) << 4));
}
// fp32 h2 buffer: 512B rows, xor swizzle keeps float2 alignment, bank-clean
__device__ __forceinline__ int h2ofs(int row, int col) {
    return row * 512 + ((col * 4) ^ ((row & 7) << 5));
}
__device__ __forceinline__ void split_pack(float a, float b, uint32_t& hi, uint32_t& lo) {
    __nv_bfloat16 ha = __float2bfloat16(a), hb = __float2bfloat16(b);
    __nv_bfloat162 h2 = __halves2bfloat162(ha, hb);
    hi = *reinterpret_cast<uint32_t*>(&h2);
    __nv_bfloat162 l2 = __floats2bfloat162_rn(a - __bfloat162float(ha), b - __bfloat162float(hb));
    lo = *reinterpret_cast<uint32_t*>(&l2);
}
__device__ __forceinline__ void mma16816(float* c, uint32_t a0, uint32_t a1, uint32_t a2,
                                         uint32_t a3, uint32_t b0, uint32_t b1) {
    asm volatile("mma.sync.aligned.m16n8k16.row.col.f32.bf16.bf16.f32 "
                 "{%0,%1,%2,%3}, {%4,%5,%6,%7}, {%8,%9}, {%0,%1,%2,%3};"
                 : "+f"(c[0]), "+f"(c[1]), "+f"(c[2]), "+f"(c[3])
                 : "r"(a0), "r"(a1), "r"(a2), "r"(a3), "r"(b0), "r"(b1));
}
__device__ __forceinline__ void mma3(float* acc, const uint32_t ah[4], const uint32_t al[4],
                                     const char* BH, const char* BL, int n, int o0) {
    uint32_t bh0 = *(const uint32_t*)(BH + swb(n, o0));
    uint32_t bh1 = *(const uint32_t*)(BH + swb(n, o0 + 16));
    uint32_t bl0 = *(const uint32_t*)(BL + swb(n, o0));
    uint32_t bl1 = *(const uint32_t*)(BL + swb(n, o0 + 16));
    mma16816(acc, ah[0], ah[1], ah[2], ah[3], bh0, bh1);
    mma16816(acc, al[0], al[1], al[2], al[3], bh0, bh1);
    mma16816(acc, ah[0], ah[1], ah[2], ah[3], bl0, bl1);
}
__device__ __forceinline__ void load_afrag(uint32_t f[4], const char* base, int lr, int o0) {
    f[0] = *(const uint32_t*)(base + swb(lr, o0));
    f[1] = *(const uint32_t*)(base + swb(lr + 8, o0));
    f[2] = *(const uint32_t*)(base + swb(lr, o0 + 16));
    f[3] = *(const uint32_t*)(base + swb(lr + 8, o0 + 16));
}

// ============================================================================
// Prep kernel: build split/swizzled bf16 hi/lo weight images. 448 x 256.
// ============================================================================
__global__ void prep_kernel(const float* __restrict__ W1,
                            const float* __restrict__ Wg,
                            const float* __restrict__ W2)
{
    int i = blockIdx.x * 256 + threadIdx.x;   // 0 .. 114687
    float v;
    char *dh, *dl;
    int o;
    if (i < 32768) {                           // B1 = [W1e | Wge]
        int n = i >> 7, k = i & 127;
        v = (n < 128) ? W1[(size_t)(256 + k) * 128 + n]
                      : Wg[(size_t)(256 + k) * 128 + (n - 128)];
        o = swb(n, 2 * k); dh = g_B1H_; dl = g_B1L_;
    } else if (i < 49152) {                    // W2
        int j = i - 32768;
        int n = j >> 7, k = j & 127;
        v = W2[(size_t)k * 128 + n];
        o = swb(n, 2 * k); dh = g_W2H_; dl = g_W2L_;
    } else {                                   // node weights, q = 0 (W1) / 1 (Wg)
        int j = i - 49152;
        int q = j >> 15; j &= 32767;
        int n = j >> 7, k = j & 127;
        const float* W = q ? Wg : W1;
        v = (n < 128) ? W[(size_t)k * 128 + n]
                      : W[(size_t)(128 + k) * 128 + (n - 128)];
        o = swb(n, 2 * k); dh = g_BNH_[q]; dl = g_BNL_[q];
    }
    __nv_bfloat16 h = __float2bfloat16(v);
    *(__nv_bfloat16*)(dh + o) = h;
    *(__nv_bfloat16*)(dl + o) = __float2bfloat16(v - __bfloat162float(h));
}

// ============================================================================
// Node kernel: 512 threads, 256-node tiles, 4 passes (q x n-half),
// B streamed per pass, warp-private A rows (no block syncs in tile loop).
// smem: BH 32K | BL 32K | AH 64K | AL 64K = 196608
// ============================================================================
__global__ __launch_bounds__(512, 1)
void node_mma_kernel(const float* __restrict__ x)
{
    extern __shared__ char sm[];
    char* BH = sm;
    char* BL = sm + 32768;
    char* AH = sm + 65536;
    char* AL = sm + 131072;

    const int tid = threadIdx.x;
    const int w = tid >> 5, lane = tid & 31;
    const int g = lane >> 2, t = lane & 3;
    const int lr = w * 16 + g;

    for (int pass = 0; pass < 4; pass++) {
        const int q = pass >> 1, nh = pass & 1;
        __syncthreads();
        for (int i = tid; i < 2048; i += 512) {
            ((float4*)BH)[i] = ((const float4*)(g_BNH_[q] + nh * 32768))[i];
            ((float4*)BL)[i] = ((const float4*)(g_BNL_[q] + nh * 32768))[i];
        }
        __syncthreads();

        for (int tile = blockIdx.x; tile < NODE_TILES2; tile += gridDim.x) {
            // stage this warp's own 16 rows of x (bf16 hi/lo)
            #pragma unroll
            for (int i = 0; i < 16; i++) {
                int r = w * 16 + i;
                int node = tile * 256 + r;
                float4 v = (node < NN) ? *(const float4*)(x + (size_t)node * 128 + lane * 4)
                                       : make_float4(0.f, 0.f, 0.f, 0.f);
                uint32_t h0, l0, h1, l1;
                split_pack(v.x, v.y, h0, l0);
                split_pack(v.z, v.w, h1, l1);
                int o = swb(r, 8 * lane);
                *(uint32_t*)(AH + o) = h0; *(uint32_t*)(AH + o + 4) = h1;
                *(uint32_t*)(AL + o) = l0; *(uint32_t*)(AL + o + 4) = l1;
            }
            __syncwarp();

            float acc[16][4];
            #pragma unroll
            for (int j = 0; j < 16; j++)
                #pragma unroll
                for (int c = 0; c < 4; c++) acc[j][c] = 0.f;
            #pragma unroll
            for (int s = 0; s < 8; s++) {
                int o0 = 32 * s + 4 * t;
                uint32_t ah[4], al[4];
                load_afrag(ah, AH, lr, o0);
                load_afrag(al, AL, lr, o0);
                #pragma unroll
                for (int j = 0; j < 16; j++)
                    mma3(acc[j], ah, al, BH, BL, j * 8 + g, o0);
            }
            const int n1 = tile * 256 + lr;
            const int n2 = n1 + 8;
            float* b1p = g_T + (size_t)n1 * 512 + q * 256 + nh * 128;
            float* b2p = g_T + (size_t)n2 * 512 + q * 256 + nh * 128;
            #pragma unroll
            for (int j = 0; j < 16; j++) {
                int col = j * 8 + 2 * t;
                if (n1 < NN) *(float2*)(b1p + col) = make_float2(acc[j][0], acc[j][1]);
                if (n2 < NN) *(float2*)(b2p + col) = make_float2(acc[j][2], acc[j][3]);
            }
            __syncwarp();
        }
    }
}

// ============================================================================
// Edge kernel: 512 threads, 128 edges/tile, warp-specialized:
//   warps 0-7  (h):    acc_h, LN+GELU, A2 staging, GEMM2, h2 -> smem
//   warps 8-15 (gate): acc_g, sigmoid in regs, combine + final LN + store
// smem: B1H 64K | B1L 64K | AH 32K | AL 32K (A1 -> A2 -> h2 fp32) | W2buf 32K
// ============================================================================
__global__ __launch_bounds__(512, 1)
void edge_mma_kernel(const int* __restrict__ ei, const float* __restrict__ ea,
                     const float* __restrict__ b1, const float* __restrict__ g1,
                     const float* __restrict__ be1, const float* __restrict__ b2,
                     const float* __restrict__ bg, const float* __restrict__ gn,
                     const float* __restrict__ bn, float* __restrict__ out)
{
    extern __shared__ char sm[];
    char* B1H = sm;
    char* B1L = sm + 65536;
    char* AH  = sm + 131072;
    char* AL  = sm + 163840;
    char* W2H = sm + 196608;
    char* W2L = sm + 212992;
    char* H2  = AH;                 // fp32 overlay, 64KB (AH+AL)

    const int tid = threadIdx.x;
    const int w = tid >> 5, lane = tid & 31;
    const int g = lane >> 2, t = lane & 3;
    const int rg = w & 7;
    const bool isH = (w < 8);
    const int lr = rg * 16 + g;

    // copy persistent B1 image
    for (int i = tid; i < 8192; i += 512) {
        ((float4*)B1H)[i] = ((const float4*)g_B1H_)[i];
        ((float4*)B1L)[i] = ((const float4*)g_B1L_)[i];
    }

    for (int tile = blockIdx.x; tile < EDGE_TILES; tile += gridDim.x) {
        __syncthreads();   // prev-tile h2 reads done (and initial B1 copy on first iter)
        // ---- stage A1: warp w stages rows w*8 .. w*8+7 ----
        #pragma unroll
        for (int i = 0; i < 8; i++) {
            int r = w * 8 + i;
            float4 v = *(const float4*)(ea + (size_t)(tile * 128 + r) * 128 + lane * 4);
            uint32_t h0, l0, h1, l1;
            split_pack(v.x, v.y, h0, l0);
            split_pack(v.z, v.w, h1, l1);
            int o = swb(r, 8 * lane);
            *(uint32_t*)(AH + o) = h0; *(uint32_t*)(AH + o + 4) = h1;
            *(uint32_t*)(AL + o) = l0; *(uint32_t*)(AL + o + 4) = l1;
        }
        __syncthreads();

        // ---- gathers + bias init (role-split) ----
        const int e1 = tile * 128 + lr;
        const int e2 = e1 + 8;
        const int is1 = ei[e1], id1 = ei[NE + e1];
        const int is2 = ei[e2], id2 = ei[NE + e2];
        const int offs = isH ? 0 : 256;
        const int offd = isH ? 128 : 384;
        const float* T1s = g_T + (size_t)is1 * 512 + offs;
        const float* T1d = g_T + (size_t)id1 * 512 + offd;
        const float* T2s = g_T + (size_t)is2 * 512 + offs;
        const float* T2d = g_T + (size_t)id2 * 512 + offd;
        const float* bias = isH ? b1 : bg;

        float acc[16][4];
        #pragma unroll
        for (int j = 0; j < 16; j++) {
            int col = j * 8 + 2 * t;
            float2 bb = *(const float2*)(bias + col);
            float2 p1 = *(const float2*)(T1s + col);
            float2 q1 = *(const float2*)(T1d + col);
            float2 p2 = *(const float2*)(T2s + col);
            float2 q2 = *(const float2*)(T2d + col);
            acc[j][0] = bb.x + p1.x + q1.x;  acc[j][1] = bb.y + p1.y + q1.y;
            acc[j][2] = bb.x + p2.x + q2.x;  acc[j][3] = bb.y + p2.y + q2.y;
        }

        // ---- GEMM1 (h-warps: B rows 0..127; gate-warps: 128..255) ----
        const int nbase = isH ? 0 : 128;
        #pragma unroll
        for (int s = 0; s < 8; s++) {
            int o0 = 32 * s + 4 * t;
            uint32_t ah[4], al[4];
            load_afrag(ah, AH, lr, o0);
            load_afrag(al, AL, lr, o0);
            #pragma unroll
            for (int j = 0; j < 16; j++)
                mma3(acc[j], ah, al, B1H, B1L, nbase + j * 8 + g, o0);
        }

        // ---- per-role nonlinearity in registers ----
        uint32_t a2w[16][2];     // h-warps: packed A2 words (hi,lo) per j
        if (isH) {
            float s1 = 0.f, q1 = 0.f, s2 = 0.f, q2 = 0.f;
            #pragma unroll
            for (int j = 0; j < 16; j++) {
                s1 += acc[j][0] + acc[j][1];
                q1 += acc[j][0] * acc[j][0] + acc[j][1] * acc[j][1];
                s2 += acc[j][2] + acc[j][3];
                q2 += acc[j][2] * acc[j][2] + acc[j][3] * acc[j][3];
            }
            #pragma unroll
            for (int o = 1; o <= 2; o <<= 1) {
                s1 += __shfl_xor_sync(0xFFFFFFFFu, s1, o);
                q1 += __shfl_xor_sync(0xFFFFFFFFu, q1, o);
                s2 += __shfl_xor_sync(0xFFFFFFFFu, s2, o);
                q2 += __shfl_xor_sync(0xFFFFFFFFu, q2, o);
            }
            float mu1 = s1 * (1.f / 128.f), rs1 = rsqrtf(q1 * (1.f / 128.f) - mu1 * mu1 + EPSC);
            float mu2 = s2 * (1.f / 128.f), rs2 = rsqrtf(q2 * (1.f / 128.f) - mu2 * mu2 + EPSC);
            #pragma unroll
            for (int j = 0; j < 16; j++) {
                int col = j * 8 + 2 * t;
                float2 gv = *(const float2*)(g1 + col);
                float2 bv = *(const float2*)(be1 + col);
                float y0 = (acc[j][0] - mu1) * rs1 * gv.x + bv.x;
                float y1 = (acc[j][1] - mu1) * rs1 * gv.y + bv.y;
                float y2 = (acc[j][2] - mu2) * rs2 * gv.x + bv.x;
                float y3 = (acc[j][3] - mu2) * rs2 * gv.y + bv.y;
                acc[j][0] = 0.5f * y0 * (1.f + erff(y0 * SQRT1_2));
                acc[j][1] = 0.5f * y1 * (1.f + erff(y1 * SQRT1_2));
                acc[j][2] = 0.5f * y2 * (1.f + erff(y2 * SQRT1_2));
                acc[j][3] = 0.5f * y3 * (1.f + erff(y3 * SQRT1_2));
            }
        } else {
            #pragma unroll
            for (int j = 0; j < 16; j++)
                #pragma unroll
                for (int c = 0; c < 4; c++)
                    acc[j][c] = 1.f / (1.f + expf(-acc[j][c]));   // gate stays in regs
        }
        __syncthreads();   // all A1 fragment reads complete before overwrite

        // ---- h-warps: write A2 (bf16 hi/lo) into A region (own rows) ----
        float acc2[16][4];
        if (isH) {
            #pragma unroll
            for (int j = 0; j < 16; j++) {
                uint32_t h0, l0, h1, l1;
                split_pack(acc[j][0], acc[j][1], h0, l0);
                split_pack(acc[j][2], acc[j][3], h1, l1);
                int b = 16 * j + 4 * t;
                *(uint32_t*)(AH + swb(lr, b))     = h0;
                *(uint32_t*)(AL + swb(lr, b))     = l0;
                *(uint32_t*)(AH + swb(lr + 8, b)) = h1;
                *(uint32_t*)(AL + swb(lr + 8, b)) = l1;
            }
            #pragma unroll
            for (int j = 0; j < 16; j++)
                #pragma unroll
                for (int c = 0; c < 4; c++) acc2[j][c] = 0.f;
        }

        // ---- GEMM2 in two W2 n-halves (h-warps compute; everyone copies) ----
        #pragma unroll
        for (int nh = 0; nh < 2; nh++) {
            __syncthreads();   // nh=0: A2 visible; nh=1: prior half's reads done
            for (int i = tid; i < 1024; i += 512) {
                ((float4*)W2H)[i] = ((const float4*)(g_W2H_ + nh * 16384))[i];
                ((float4*)W2L)[i] = ((const float4*)(g_W2L_ + nh * 16384))[i];
            }
            __syncthreads();
            if (isH) {
                #pragma unroll
                for (int s = 0; s < 8; s++) {
                    int o0 = 32 * s + 4 * t;
                    uint32_t ah[4], al[4];
                    load_afrag(ah, AH, lr, o0);
                    load_afrag(al, AL, lr, o0);
                    #pragma unroll
                    for (int jl = 0; jl < 8; jl++)
                        mma3(acc2[nh * 8 + jl], ah, al, W2H, W2L, jl * 8 + g, o0);
                }
            }
        }
        __syncthreads();   // h-warps' A2 reads done -> safe to overlay h2

        // ---- h-warps: h2 + b2 -> smem fp32 ----
        if (isH) {
            #pragma unroll
            for (int j = 0; j < 16; j++) {
                int col = j * 8 + 2 * t;
                float2 bv = *(const float2*)(b2 + col);
                *(float2*)(H2 + h2ofs(lr, col)) =
                    make_float2(acc2[j][0] + bv.x, acc2[j][1] + bv.y);
                *(float2*)(H2 + h2ofs(lr + 8, col)) =
                    make_float2(acc2[j][2] + bv.x, acc2[j][3] + bv.y);
            }
        }
        __syncthreads();

        // ---- gate-warps: combine + final LN + store ----
        if (!isH) {
            float r[16][4];
            #pragma unroll
            for (int j = 0; j < 16; j++) {
                int col = j * 8 + 2 * t;
                float2 hA = *(const float2*)(H2 + h2ofs(lr, col));
                float2 hB = *(const float2*)(H2 + h2ofs(lr + 8, col));
                float2 eA = *(const float2*)(ea + (size_t)e1 * 128 + col);
                float2 eB = *(const float2*)(ea + (size_t)e2 * 128 + col);
                r[j][0] = hA.x * acc[j][0] + eA.x;
                r[j][1] = hA.y * acc[j][1] + eA.y;
                r[j][2] = hB.x * acc[j][2] + eB.x;
                r[j][3] = hB.y * acc[j][3] + eB.y;
            }
            float s1 = 0.f, q1 = 0.f, s2 = 0.f, q2 = 0.f;
            #pragma unroll
            for (int j = 0; j < 16; j++) {
                s1 += r[j][0] + r[j][1];
                q1 += r[j][0] * r[j][0] + r[j][1] * r[j][1];
                s2 += r[j][2] + r[j][3];
                q2 += r[j][2] * r[j][2] + r[j][3] * r[j][3];
            }
            #pragma unroll
            for (int o = 1; o <= 2; o <<= 1) {
                s1 += __shfl_xor_sync(0xFFFFFFFFu, s1, o);
                q1 += __shfl_xor_sync(0xFFFFFFFFu, q1, o);
                s2 += __shfl_xor_sync(0xFFFFFFFFu, s2, o);
                q2 += __shfl_xor_sync(0xFFFFFFFFu, q2, o);
            }
            float mu1 = s1 * (1.f / 128.f), rs1 = rsqrtf(q1 * (1.f / 128.f) - mu1 * mu1 + EPSC);
            float mu2 = s2 * (1.f / 128.f), rs2 = rsqrtf(q2 * (1.f / 128.f) - mu2 * mu2 + EPSC);
            #pragma unroll
            for (int j = 0; j < 16; j++) {
                int col = j * 8 + 2 * t;
                float2 gv = *(const float2*)(gn + col);
                float2 bv = *(const float2*)(bn + col);
                float2 o1, o2;
                o1.x = (r[j][0] - mu1) * rs1 * gv.x + bv.x;
                o1.y = (r[j][1] - mu1) * rs1 * gv.y + bv.y;
                o2.x = (r[j][2] - mu2) * rs2 * gv.x + bv.x;
                o2.y = (r[j][3] - mu2) * rs2 * gv.y + bv.y;
                *(float2*)(out + (size_t)e1 * 128 + col) = o1;
                *(float2*)(out + (size_t)e2 * 128 + col) = o2;
            }
        }
    }
}

// ---------------------------------------------------------------------------
extern "C" void kernel_launch(void* const* d_in, const int* in_sizes, int n_in,
                              void* d_out, int out_size)
{
    const float* x   = (const float*)d_in[0];
    const int*   ei  = (const int*)d_in[1];
    const float* ea  = (const float*)d_in[2];
    const float* W1  = (const float*)d_in[3];
    const float* b1  = (const float*)d_in[4];
    const float* g1  = (const float*)d_in[5];
    const float* be1 = (const float*)d_in[6];
    const float* W2  = (const float*)d_in[7];
    const float* b2  = (const float*)d_in[8];
    const float* Wg  = (const float*)d_in[9];
    const float* bg  = (const float*)d_in[10];
    const float* gn  = (const float*)d_in[11];
    const float* bn  = (const float*)d_in[12];
    float*       out = (float*)d_out;

    const int node_smem = 196608;
    const int edge_smem = 229376;
    cudaFuncSetAttribute(node_mma_kernel, cudaFuncAttributeMaxDynamicSharedMemorySize, node_smem);
    cudaFuncSetAttribute(edge_mma_kernel, cudaFuncAttributeMaxDynamicSharedMemorySize, edge_smem);

    prep_kernel<<<448, 256>>>(W1, Wg, W2);
    node_mma_kernel<<<GRID_P, 512, node_smem>>>(x);
    edge_mma_kernel<<<GRID_P, 512, edge_smem>>>(ei, ea, b1, g1, be1, b2, bg, gn, bn, out);
}

// round 8
// speedup vs baseline: 1.2310x; 1.2310x over previous
#include <cuda_runtime.h>
#include <cuda_fp16.h>
#include <stdint.h>
#include <math.h>

#define NN 100000
#define NE 524288
#define EPSC 1e-5f
#define EDGE_TILES 4096
#define NODE_TILES 391
#define GRID_P 148
#define SQRT1_2 0.70710678118654752440f

// g_T[n][0:128]=x@W1[0:128]  [128:256]=x@W1[128:256]  [256:384]=x@Wg[0:128]  [384:512]=x@Wg[128:256]
static __device__ float g_T[(size_t)NN * 512];

// Pre-swizzled fp16 weight images (prep_kernel)
static __device__ char g_B1f_[65536];      // [W1e|Wge] 256n x 128k
static __device__ char g_W2f_[32768];      // W2 128n x 128k
static __device__ char g_BNf_[2][65536];   // node W1 / Wg halves, 256n x 128k

// ---------------- helpers ----------------
__device__ __forceinline__ int swb(int row, int b) {      // 256B rows, xor swizzle
    return row * 256 + (b ^ ((row & 7) << 4));
}
__device__ __forceinline__ int h2ofs(int row, int col) {  // fp32 512B rows
    return row * 512 + ((col * 4) ^ ((row & 7) << 5));
}
__device__ __forceinline__ void split_packh(float a, float b, uint32_t& hi, uint32_t& lo) {
    __half ha = __float2half_rn(a), hb = __float2half_rn(b);
    __half2 h2 = __halves2half2(ha, hb);
    hi = *reinterpret_cast<uint32_t*>(&h2);
    __half2 l2 = __floats2half2_rn(a - __half2float(ha), b - __half2float(hb));
    lo = *reinterpret_cast<uint32_t*>(&l2);
}
__device__ __forceinline__ void mma16816h(float* c, uint32_t a0, uint32_t a1, uint32_t a2,
                                          uint32_t a3, uint32_t b0, uint32_t b1) {
    asm volatile("mma.sync.aligned.m16n8k16.row.col.f32.f16.f16.f32 "
                 "{%0,%1,%2,%3}, {%4,%5,%6,%7}, {%8,%9}, {%0,%1,%2,%3};"
                 : "+f"(c[0]), "+f"(c[1]), "+f"(c[2]), "+f"(c[3])
                 : "r"(a0), "r"(a1), "r"(a2), "r"(a3), "r"(b0), "r"(b1));
}
// 2-term fp16 split: acc += Ahi*B + Alo*B
__device__ __forceinline__ void mma2(float* acc, const uint32_t ah[4], const uint32_t al[4],
                                     const char* B, int n, int o0) {
    uint32_t b0 = *(const uint32_t*)(B + swb(n, o0));
    uint32_t b1 = *(const uint32_t*)(B + swb(n, o0 + 16));
    mma16816h(acc, ah[0], ah[1], ah[2], ah[3], b0, b1);
    mma16816h(acc, al[0], al[1], al[2], al[3], b0, b1);
}
__device__ __forceinline__ void load_afrag(uint32_t f[4], const char* base, int lr, int o0) {
    f[0] = *(const uint32_t*)(base + swb(lr, o0));
    f[1] = *(const uint32_t*)(base + swb(lr + 8, o0));
    f[2] = *(const uint32_t*)(base + swb(lr, o0 + 16));
    f[3] = *(const uint32_t*)(base + swb(lr + 8, o0 + 16));
}
#define PAIR_BAR(id) asm volatile("bar.sync %0, 64;" :: "r"(id) : "memory")

// ============================================================================
// Prep kernel: build swizzled fp16 weight images. 448 x 256 = 114688 elems.
// ============================================================================
__global__ void prep_kernel(const float* __restrict__ W1,
                            const float* __restrict__ Wg,
                            const float* __restrict__ W2)
{
    int i = blockIdx.x * 256 + threadIdx.x;
    float v;
    char* dst;
    int o;
    if (i < 32768) {                           // B1 = [W1e | Wge]
        int n = i >> 7, k = i & 127;
        v = (n < 128) ? W1[(size_t)(256 + k) * 128 + n]
                      : Wg[(size_t)(256 + k) * 128 + (n - 128)];
        o = swb(n, 2 * k); dst = g_B1f_;
    } else if (i < 49152) {                    // W2
        int j = i - 32768;
        int n = j >> 7, k = j & 127;
        v = W2[(size_t)k * 128 + n];
        o = swb(n, 2 * k); dst = g_W2f_;
    } else {                                   // node weights q=0(W1)/1(Wg)
        int j = i - 49152;
        int q = j >> 15; j &= 32767;
        int n = j >> 7, k = j & 127;
        const float* W = q ? Wg : W1;
        v = (n < 128) ? W[(size_t)k * 128 + n]
                      : W[(size_t)(128 + k) * 128 + (n - 128)];
        o = swb(n, 2 * k); dst = g_BNf_[q];
    }
    *(__half*)(dst + o) = __float2half_rn(v);
}

// ============================================================================
// Node kernel: 512 threads, 16 warps x 16 rows = 256-node tiles. B resident
// per q-pass. No block syncs inside tile loop.
// smem: B 64K | AH 64K | AL 64K = 196608
// ============================================================================
__global__ __launch_bounds__(512, 1)
void node_mma_kernel(const float* __restrict__ x)
{
    extern __shared__ char sm[];
    char* B  = sm;
    char* AH = sm + 65536;
    char* AL = sm + 131072;

    const int tid = threadIdx.x;
    const int w = tid >> 5, lane = tid & 31;
    const int g = lane >> 2, t = lane & 3;
    const int lr = w * 16 + g;

    for (int q = 0; q < 2; q++) {
        __syncthreads();
        for (int i = tid; i < 4096; i += 512)
            ((float4*)B)[i] = ((const float4*)g_BNf_[q])[i];
        __syncthreads();

        for (int tile = blockIdx.x; tile < NODE_TILES; tile += gridDim.x) {
            #pragma unroll
            for (int i = 0; i < 16; i++) {
                int r = w * 16 + i;
                int node = tile * 256 + r;
                float4 v = (node < NN) ? *(const float4*)(x + (size_t)node * 128 + lane * 4)
                                       : make_float4(0.f, 0.f, 0.f, 0.f);
                uint32_t h0, l0, h1, l1;
                split_packh(v.x, v.y, h0, l0);
                split_packh(v.z, v.w, h1, l1);
                int o = swb(r, 8 * lane);
                *(uint2*)(AH + o) = make_uint2(h0, h1);
                *(uint2*)(AL + o) = make_uint2(l0, l1);
            }
            __syncwarp();

            const int n1 = tile * 256 + lr;
            const int n2 = n1 + 8;
            #pragma unroll
            for (int nh = 0; nh < 2; nh++) {
                float acc[16][4];
                #pragma unroll
                for (int j = 0; j < 16; j++)
                    #pragma unroll
                    for (int c = 0; c < 4; c++) acc[j][c] = 0.f;
                #pragma unroll
                for (int s = 0; s < 8; s++) {
                    int o0 = 32 * s + 4 * t;
                    uint32_t ah[4], al[4];
                    load_afrag(ah, AH, lr, o0);
                    load_afrag(al, AL, lr, o0);
                    #pragma unroll
                    for (int j = 0; j < 16; j++)
                        mma2(acc[j], ah, al, B, nh * 128 + j * 8 + g, o0);
                }
                float* p1 = g_T + (size_t)n1 * 512 + q * 256 + nh * 128;
                float* p2 = g_T + (size_t)n2 * 512 + q * 256 + nh * 128;
                #pragma unroll
                for (int j = 0; j < 16; j++) {
                    int col = j * 8 + 2 * t;
                    if (n1 < NN) *(float2*)(p1 + col) = make_float2(acc[j][0], acc[j][1]);
                    if (n2 < NN) *(float2*)(p2 + col) = make_float2(acc[j][2], acc[j][3]);
                }
            }
            __syncwarp();
        }
    }
}

// ============================================================================
// Edge kernel: 512 threads = 8 independent pairs {h-warp w, gate-warp w+8}.
// Pair w owns edges tile*128 + w*16 .. +15. All weights smem-resident.
// NO block syncs in tile loop; pairs sync via named barrier (1+w, 64).
// smem: B1 64K | W2 32K | AH 32K | AL 32K | H2 64K = 229376
// ============================================================================
__global__ __launch_bounds__(512, 1)
void edge_mma_kernel(const int* __restrict__ ei, const float* __restrict__ ea,
                     const float* __restrict__ b1, const float* __restrict__ g1,
                     const float* __restrict__ be1, const float* __restrict__ b2,
                     const float* __restrict__ bg, const float* __restrict__ gn,
                     const float* __restrict__ bn, float* __restrict__ out)
{
    extern __shared__ char sm[];
    char* B1 = sm;
    char* W2s = sm + 65536;
    char* AH = sm + 98304;
    char* AL = sm + 131072;
    char* H2 = sm + 163840;

    const int tid = threadIdx.x;
    const int w = tid >> 5, lane = tid & 31;
    const int g = lane >> 2, t = lane & 3;
    const int pw = w & 7;
    const bool isH = (w < 8);
    const int lr = pw * 16 + g;
    const int barid = 1 + pw;

    // stage resident weights once
    for (int i = tid; i < 4096; i += 512) ((float4*)B1)[i] = ((const float4*)g_B1f_)[i];
    for (int i = tid; i < 2048; i += 512) ((float4*)W2s)[i] = ((const float4*)g_W2f_)[i];
    __syncthreads();

    for (int tile = blockIdx.x; tile < EDGE_TILES; tile += gridDim.x) {
        // ---- stage A1: h stages rows pw*16..+7, gate stages +8..+15 ----
        #pragma unroll
        for (int i = 0; i < 8; i++) {
            int r = pw * 16 + (isH ? i : 8 + i);
            float4 v = *(const float4*)(ea + (size_t)(tile * 128 + r) * 128 + lane * 4);
            uint32_t h0, l0, h1, l1;
            split_packh(v.x, v.y, h0, l0);
            split_packh(v.z, v.w, h1, l1);
            int o = swb(r, 8 * lane);
            *(uint2*)(AH + o) = make_uint2(h0, h1);
            *(uint2*)(AL + o) = make_uint2(l0, l1);
        }
        PAIR_BAR(barid);

        // ---- gathers + bias (role-split halves of g_T) ----
        const int e1 = tile * 128 + lr;
        const int e2 = e1 + 8;
        const int is1 = ei[e1], id1 = ei[NE + e1];
        const int is2 = ei[e2], id2 = ei[NE + e2];
        const int offs = isH ? 0 : 256;
        const int offd = isH ? 128 : 384;
        const float* T1s = g_T + (size_t)is1 * 512 + offs;
        const float* T1d = g_T + (size_t)id1 * 512 + offd;
        const float* T2s = g_T + (size_t)is2 * 512 + offs;
        const float* T2d = g_T + (size_t)id2 * 512 + offd;
        const float* bias = isH ? b1 : bg;

        float acc[16][4];
        #pragma unroll
        for (int j = 0; j < 16; j++) {
            int col = j * 8 + 2 * t;
            float2 bb = *(const float2*)(bias + col);
            float2 p1 = *(const float2*)(T1s + col);
            float2 q1 = *(const float2*)(T1d + col);
            float2 p2 = *(const float2*)(T2s + col);
            float2 q2 = *(const float2*)(T2d + col);
            acc[j][0] = bb.x + p1.x + q1.x;  acc[j][1] = bb.y + p1.y + q1.y;
            acc[j][2] = bb.x + p2.x + q2.x;  acc[j][3] = bb.y + p2.y + q2.y;
        }

        // ---- GEMM1: h vs B1 rows 0..127, gate vs rows 128..255 ----
        const int nbase = isH ? 0 : 128;
        #pragma unroll
        for (int s = 0; s < 8; s++) {
            int o0 = 32 * s + 4 * t;
            uint32_t ah[4], al[4];
            load_afrag(ah, AH, lr, o0);
            load_afrag(al, AL, lr, o0);
            #pragma unroll
            for (int j = 0; j < 16; j++)
                mma2(acc[j], ah, al, B1, nbase + j * 8 + g, o0);
        }

        // ---- per-role nonlinearity ----
        if (isH) {
            float s1 = 0.f, q1 = 0.f, s2 = 0.f, q2 = 0.f;
            #pragma unroll
            for (int j = 0; j < 16; j++) {
                s1 += acc[j][0] + acc[j][1];
                q1 += acc[j][0] * acc[j][0] + acc[j][1] * acc[j][1];
                s2 += acc[j][2] + acc[j][3];
                q2 += acc[j][2] * acc[j][2] + acc[j][3] * acc[j][3];
            }
            #pragma unroll
            for (int o = 1; o <= 2; o <<= 1) {
                s1 += __shfl_xor_sync(0xFFFFFFFFu, s1, o);
                q1 += __shfl_xor_sync(0xFFFFFFFFu, q1, o);
                s2 += __shfl_xor_sync(0xFFFFFFFFu, s2, o);
                q2 += __shfl_xor_sync(0xFFFFFFFFu, q2, o);
            }
            float mu1 = s1 * (1.f / 128.f), rs1 = rsqrtf(q1 * (1.f / 128.f) - mu1 * mu1 + EPSC);
            float mu2 = s2 * (1.f / 128.f), rs2 = rsqrtf(q2 * (1.f / 128.f) - mu2 * mu2 + EPSC);
            #pragma unroll
            for (int j = 0; j < 16; j++) {
                int col = j * 8 + 2 * t;
                float2 gv = *(const float2*)(g1 + col);
                float2 bv = *(const float2*)(be1 + col);
                float y0 = (acc[j][0] - mu1) * rs1 * gv.x + bv.x;
                float y1 = (acc[j][1] - mu1) * rs1 * gv.y + bv.y;
                float y2 = (acc[j][2] - mu2) * rs2 * gv.x + bv.x;
                float y3 = (acc[j][3] - mu2) * rs2 * gv.y + bv.y;
                acc[j][0] = 0.5f * y0 * (1.f + erff(y0 * SQRT1_2));
                acc[j][1] = 0.5f * y1 * (1.f + erff(y1 * SQRT1_2));
                acc[j][2] = 0.5f * y2 * (1.f + erff(y2 * SQRT1_2));
                acc[j][3] = 0.5f * y3 * (1.f + erff(y3 * SQRT1_2));
            }
        } else {
            #pragma unroll
            for (int j = 0; j < 16; j++)
                #pragma unroll
                for (int c = 0; c < 4; c++)
                    acc[j][c] = 1.f / (1.f + expf(-acc[j][c]));   // gate stays in regs
        }
        PAIR_BAR(barid);   // pair done reading A1 -> h may overwrite with A2

        if (isH) {
            // ---- write A2 (gelu h) into pair's A rows ----
            #pragma unroll
            for (int j = 0; j < 16; j++) {
                uint32_t h0, l0, h1, l1;
                split_packh(acc[j][0], acc[j][1], h0, l0);
                split_packh(acc[j][2], acc[j][3], h1, l1);
                int b = 16 * j + 4 * t;
                *(uint32_t*)(AH + swb(lr, b))     = h0;
                *(uint32_t*)(AL + swb(lr, b))     = l0;
                *(uint32_t*)(AH + swb(lr + 8, b)) = h1;
                *(uint32_t*)(AL + swb(lr + 8, b)) = l1;
            }
            __syncwarp();
            // ---- GEMM2 vs resident W2 ----
            float acc2[16][4];
            #pragma unroll
            for (int j = 0; j < 16; j++)
                #pragma unroll
                for (int c = 0; c < 4; c++) acc2[j][c] = 0.f;
            #pragma unroll
            for (int s = 0; s < 8; s++) {
                int o0 = 32 * s + 4 * t;
                uint32_t ah[4], al[4];
                load_afrag(ah, AH, lr, o0);
                load_afrag(al, AL, lr, o0);
                #pragma unroll
                for (int j = 0; j < 16; j++)
                    mma2(acc2[j], ah, al, W2s, j * 8 + g, o0);
            }
            // ---- h2 + b2 -> H2 smem ----
            #pragma unroll
            for (int j = 0; j < 16; j++) {
                int col = j * 8 + 2 * t;
                float2 bv = *(const float2*)(b2 + col);
                *(float2*)(H2 + h2ofs(lr, col)) =
                    make_float2(acc2[j][0] + bv.x, acc2[j][1] + bv.y);
                *(float2*)(H2 + h2ofs(lr + 8, col)) =
                    make_float2(acc2[j][2] + bv.x, acc2[j][3] + bv.y);
            }
        }
        PAIR_BAR(barid);   // h2 ready

        if (!isH) {
            // ---- combine: r = h2 * gate + ea ; final LN ; store ----
            #pragma unroll
            for (int j = 0; j < 16; j++) {
                int col = j * 8 + 2 * t;
                float2 hA = *(const float2*)(H2 + h2ofs(lr, col));
                float2 hB = *(const float2*)(H2 + h2ofs(lr + 8, col));
                float2 eA = *(const float2*)(ea + (size_t)e1 * 128 + col);
                float2 eB = *(const float2*)(ea + (size_t)e2 * 128 + col);
                acc[j][0] = hA.x * acc[j][0] + eA.x;
                acc[j][1] = hA.y * acc[j][1] + eA.y;
                acc[j][2] = hB.x * acc[j][2] + eB.x;
                acc[j][3] = hB.y * acc[j][3] + eB.y;
            }
            float s1 = 0.f, q1 = 0.f, s2 = 0.f, q2 = 0.f;
            #pragma unroll
            for (int j = 0; j < 16; j++) {
                s1 += acc[j][0] + acc[j][1];
                q1 += acc[j][0] * acc[j][0] + acc[j][1] * acc[j][1];
                s2 += acc[j][2] + acc[j][3];
                q2 += acc[j][2] * acc[j][2] + acc[j][3] * acc[j][3];
            }
            #pragma unroll
            for (int o = 1; o <= 2; o <<= 1) {
                s1 += __shfl_xor_sync(0xFFFFFFFFu, s1, o);
                q1 += __shfl_xor_sync(0xFFFFFFFFu, q1, o);
                s2 += __shfl_xor_sync(0xFFFFFFFFu, s2, o);
                q2 += __shfl_xor_sync(0xFFFFFFFFu, q2, o);
            }
            float mu1 = s1 * (1.f / 128.f), rs1 = rsqrtf(q1 * (1.f / 128.f) - mu1 * mu1 + EPSC);
            float mu2 = s2 * (1.f / 128.f), rs2 = rsqrtf(q2 * (1.f / 128.f) - mu2 * mu2 + EPSC);
            #pragma unroll
            for (int j = 0; j < 16; j++) {
                int col = j * 8 + 2 * t;
                float2 gv = *(const float2*)(gn + col);
                float2 bv = *(const float2*)(bn + col);
                float2 o1, o2;
                o1.x = (acc[j][0] - mu1) * rs1 * gv.x + bv.x;
                o1.y = (acc[j][1] - mu1) * rs1 * gv.y + bv.y;
                o2.x = (acc[j][2] - mu2) * rs2 * gv.x + bv.x;
                o2.y = (acc[j][3] - mu2) * rs2 * gv.y + bv.y;
                *(float2*)(out + (size_t)e1 * 128 + col) = o1;
                *(float2*)(out + (size_t)e2 * 128 + col) = o2;
            }
        }
    }
}

// ---------------------------------------------------------------------------
extern "C" void kernel_launch(void* const* d_in, const int* in_sizes, int n_in,
                              void* d_out, int out_size)
{
    const float* x   = (const float*)d_in[0];
    const int*   ei  = (const int*)d_in[1];
    const float* ea  = (const float*)d_in[2];
    const float* W1  = (const float*)d_in[3];
    const float* b1  = (const float*)d_in[4];
    const float* g1  = (const float*)d_in[5];
    const float* be1 = (const float*)d_in[6];
    const float* W2  = (const float*)d_in[7];
    const float* b2  = (const float*)d_in[8];
    const float* Wg  = (const float*)d_in[9];
    const float* bg  = (const float*)d_in[10];
    const float* gn  = (const float*)d_in[11];
    const float* bn  = (const float*)d_in[12];
    float*       out = (float*)d_out;

    const int node_smem = 196608;
    const int edge_smem = 229376;
    cudaFuncSetAttribute(node_mma_kernel, cudaFuncAttributeMaxDynamicSharedMemorySize, node_smem);
    cudaFuncSetAttribute(edge_mma_kernel, cudaFuncAttributeMaxDynamicSharedMemorySize, edge_smem);

    prep_kernel<<<448, 256>>>(W1, Wg, W2);
    node_mma_kernel<<<GRID_P, 512, node_smem>>>(x);
    edge_mma_kernel<<<GRID_P, 512, edge_smem>>>(ei, ea, b1, g1, be1, b2, bg, gn, bn, out);
}

// round 9
// speedup vs baseline: 1.7925x; 1.4561x over previous
#include <cuda_runtime.h>
#include <cuda_fp16.h>
#include <stdint.h>
#include <math.h>

#define NN 100000
#define NE 524288
#define EPSC 1e-5f
#define EDGE_TILES 4096
#define NODE_TILES 391
#define GRID_P 148
#define SQRT1_2 0.70710678118654752440f

// g_T (fp16): [0:128]=x@W1[0:128] [128:256]=x@W1[128:256] [256:384]=x@Wg[0:128] [384:512]=x@Wg[128:256]
static __device__ __half g_T[(size_t)NN * 512];

// Pre-swizzled fp16 weight images
static __device__ char g_B1f_[65536];      // [W1e|Wge] 256n x 128k
static __device__ char g_W2f_[32768];      // W2 128n x 128k
static __device__ char g_BNf_[2][65536];   // node W1 / Wg, 256n x 128k

// ---------------- helpers ----------------
__device__ __forceinline__ int swb(int row, int b) {      // 256B rows, xor swizzle
    return row * 256 + (b ^ ((row & 7) << 4));
}
__device__ __forceinline__ int gofs(int row, int col) {   // fp32 gate buf, 256B rows
    return row * 256 + ((col * 4) ^ ((row & 7) << 5));
}
__device__ __forceinline__ void split_packh(float a, float b, uint32_t& hi, uint32_t& lo) {
    __half ha = __float2half_rn(a), hb = __float2half_rn(b);
    __half2 h2 = __halves2half2(ha, hb);
    hi = *reinterpret_cast<uint32_t*>(&h2);
    __half2 l2 = __floats2half2_rn(a - __half2float(ha), b - __half2float(hb));
    lo = *reinterpret_cast<uint32_t*>(&l2);
}
__device__ __forceinline__ void mma16816h(float* c, uint32_t a0, uint32_t a1, uint32_t a2,
                                          uint32_t a3, uint32_t b0, uint32_t b1) {
    asm volatile("mma.sync.aligned.m16n8k16.row.col.f32.f16.f16.f32 "
                 "{%0,%1,%2,%3}, {%4,%5,%6,%7}, {%8,%9}, {%0,%1,%2,%3};"
                 : "+f"(c[0]), "+f"(c[1]), "+f"(c[2]), "+f"(c[3])
                 : "r"(a0), "r"(a1), "r"(a2), "r"(a3), "r"(b0), "r"(b1));
}
__device__ __forceinline__ void mma2(float* acc, const uint32_t ah[4], const uint32_t al[4],
                                     const char* B, int n, int o0) {
    uint32_t b0 = *(const uint32_t*)(B + swb(n, o0));
    uint32_t b1 = *(const uint32_t*)(B + swb(n, o0 + 16));
    mma16816h(acc, ah[0], ah[1], ah[2], ah[3], b0, b1);
    mma16816h(acc, al[0], al[1], al[2], al[3], b0, b1);
}
__device__ __forceinline__ void load_afrag(uint32_t f[4], const char* base, int lr, int o0) {
    f[0] = *(const uint32_t*)(base + swb(lr, o0));
    f[1] = *(const uint32_t*)(base + swb(lr + 8, o0));
    f[2] = *(const uint32_t*)(base + swb(lr, o0 + 16));
    f[3] = *(const uint32_t*)(base + swb(lr + 8, o0 + 16));
}
#define PAIR_BAR(id) asm volatile("bar.sync %0, 64;" :: "r"(id) : "memory")

// ============================================================================
// Prep kernel: build swizzled fp16 weight images.
// ============================================================================
__global__ void prep_kernel(const float* __restrict__ W1,
                            const float* __restrict__ Wg,
                            const float* __restrict__ W2)
{
    int i = blockIdx.x * 256 + threadIdx.x;
    float v;
    char* dst;
    int o;
    if (i < 32768) {
        int n = i >> 7, k = i & 127;
        v = (n < 128) ? W1[(size_t)(256 + k) * 128 + n]
                      : Wg[(size_t)(256 + k) * 128 + (n - 128)];
        o = swb(n, 2 * k); dst = g_B1f_;
    } else if (i < 49152) {
        int j = i - 32768;
        int n = j >> 7, k = j & 127;
        v = W2[(size_t)k * 128 + n];
        o = swb(n, 2 * k); dst = g_W2f_;
    } else {
        int j = i - 49152;
        int q = j >> 15; j &= 32767;
        int n = j >> 7, k = j & 127;
        const float* W = q ? Wg : W1;
        v = (n < 128) ? W[(size_t)k * 128 + n]
                      : W[(size_t)(128 + k) * 128 + (n - 128)];
        o = swb(n, 2 * k); dst = g_BNf_[q];
    }
    *(__half*)(dst + o) = __float2half_rn(v);
}

// ============================================================================
// Node kernel: 512 threads, 256-node tiles, fp16 g_T output.
// smem: B 64K | AH 64K | AL 64K = 196608
// ============================================================================
__global__ __launch_bounds__(512, 1)
void node_mma_kernel(const float* __restrict__ x)
{
    extern __shared__ char sm[];
    char* B  = sm;
    char* AH = sm + 65536;
    char* AL = sm + 131072;

    const int tid = threadIdx.x;
    const int w = tid >> 5, lane = tid & 31;
    const int g = lane >> 2, t = lane & 3;
    const int lr = w * 16 + g;

    for (int q = 0; q < 2; q++) {
        __syncthreads();
        for (int i = tid; i < 4096; i += 512)
            ((float4*)B)[i] = ((const float4*)g_BNf_[q])[i];
        __syncthreads();

        for (int tile = blockIdx.x; tile < NODE_TILES; tile += gridDim.x) {
            #pragma unroll
            for (int i = 0; i < 16; i++) {
                int r = w * 16 + i;
                int node = tile * 256 + r;
                float4 v = (node < NN) ? *(const float4*)(x + (size_t)node * 128 + lane * 4)
                                       : make_float4(0.f, 0.f, 0.f, 0.f);
                uint32_t h0, l0, h1, l1;
                split_packh(v.x, v.y, h0, l0);
                split_packh(v.z, v.w, h1, l1);
                int o = swb(r, 8 * lane);
                *(uint2*)(AH + o) = make_uint2(h0, h1);
                *(uint2*)(AL + o) = make_uint2(l0, l1);
            }
            __syncwarp();

            const int n1 = tile * 256 + lr;
            const int n2 = n1 + 8;
            #pragma unroll
            for (int nh = 0; nh < 2; nh++) {
                float acc[16][4];
                #pragma unroll
                for (int j = 0; j < 16; j++)
                    #pragma unroll
                    for (int c = 0; c < 4; c++) acc[j][c] = 0.f;
                #pragma unroll
                for (int s = 0; s < 8; s++) {
                    int o0 = 32 * s + 4 * t;
                    uint32_t ah[4], al[4];
                    load_afrag(ah, AH, lr, o0);
                    load_afrag(al, AL, lr, o0);
                    #pragma unroll
                    for (int j = 0; j < 16; j++)
                        mma2(acc[j], ah, al, B, nh * 128 + j * 8 + g, o0);
                }
                __half* p1 = g_T + (size_t)n1 * 512 + q * 256 + nh * 128;
                __half* p2 = g_T + (size_t)n2 * 512 + q * 256 + nh * 128;
                #pragma unroll
                for (int j = 0; j < 16; j++) {
                    int col = j * 8 + 2 * t;
                    if (n1 < NN) *(__half2*)(p1 + col) = __floats2half2_rn(acc[j][0], acc[j][1]);
                    if (n2 < NN) *(__half2*)(p2 + col) = __floats2half2_rn(acc[j][2], acc[j][3]);
                }
            }
            __syncwarp();
        }
    }
}

// ============================================================================
// Edge kernel: 512 threads = 8 pairs {h-warp w, gate-warp w+8}; pair owns 16
// edges. GEMM2 + epilogue split across the pair (h: cols 0-63, gate: 64-127).
// smem: B1 64K | W2 32K | AH 32K | AL 32K | G 32K | S 2K = 198656
// ============================================================================
__global__ __launch_bounds__(512, 1)
void edge_mma_kernel(const int* __restrict__ ei, const float* __restrict__ ea,
                     const float* __restrict__ b1, const float* __restrict__ g1,
                     const float* __restrict__ be1, const float* __restrict__ b2,
                     const float* __restrict__ bg, const float* __restrict__ gn,
                     const float* __restrict__ bn, float* __restrict__ out,
                     int tile0)
{
    extern __shared__ char sm[];
    char* B1  = sm;
    char* W2s = sm + 65536;
    char* AH  = sm + 98304;
    char* AL  = sm + 131072;
    char* G   = sm + 163840;
    float* S  = (float*)(sm + 196608);

    const int tid = threadIdx.x;
    const int w = tid >> 5, lane = tid & 31;
    const int g = lane >> 2, t = lane & 3;
    const int pw = w & 7;
    const bool isH = (w < 8);
    const int lr = pw * 16 + g;
    const int barid = 1 + pw;

    for (int i = tid; i < 4096; i += 512) ((float4*)B1)[i] = ((const float4*)g_B1f_)[i];
    for (int i = tid; i < 2048; i += 512) ((float4*)W2s)[i] = ((const float4*)g_W2f_)[i];
    __syncthreads();

    const int tile_end = tile0 + EDGE_TILES / 4;
    for (int tile = tile0 + blockIdx.x; tile < tile_end; tile += gridDim.x) {
        // ---- stage A1: h stages rows pw*16..+7, gate +8..+15 ----
        #pragma unroll
        for (int i = 0; i < 8; i++) {
            int r = pw * 16 + (isH ? i : 8 + i);
            float4 v = *(const float4*)(ea + (size_t)(tile * 128 + r) * 128 + lane * 4);
            uint32_t h0, l0, h1, l1;
            split_packh(v.x, v.y, h0, l0);
            split_packh(v.z, v.w, h1, l1);
            int o = swb(r, 8 * lane);
            *(uint2*)(AH + o) = make_uint2(h0, h1);
            *(uint2*)(AL + o) = make_uint2(l0, l1);
        }
        PAIR_BAR(barid);

        // ---- gathers (fp16 g_T, L2-resident) + bias ----
        const int e1 = tile * 128 + lr;
        const int e2 = e1 + 8;
        const int is1 = ei[e1], id1 = ei[NE + e1];
        const int is2 = ei[e2], id2 = ei[NE + e2];
        const int offs = isH ? 0 : 256;
        const int offd = isH ? 128 : 384;
        const __half* T1s = g_T + (size_t)is1 * 512 + offs;
        const __half* T1d = g_T + (size_t)id1 * 512 + offd;
        const __half* T2s = g_T + (size_t)is2 * 512 + offs;
        const __half* T2d = g_T + (size_t)id2 * 512 + offd;
        const float* bias = isH ? b1 : bg;

        float acc[16][4];
        #pragma unroll
        for (int j = 0; j < 16; j++) {
            int col = j * 8 + 2 * t;
            float2 bb = *(const float2*)(bias + col);
            float2 p1 = __half22float2(*(const __half2*)(T1s + col));
            float2 q1 = __half22float2(*(const __half2*)(T1d + col));
            float2 p2 = __half22float2(*(const __half2*)(T2s + col));
            float2 q2 = __half22float2(*(const __half2*)(T2d + col));
            acc[j][0] = bb.x + p1.x + q1.x;  acc[j][1] = bb.y + p1.y + q1.y;
            acc[j][2] = bb.x + p2.x + q2.x;  acc[j][3] = bb.y + p2.y + q2.y;
        }

        // ---- GEMM1 ----
        const int nbase = isH ? 0 : 128;
        #pragma unroll
        for (int s = 0; s < 8; s++) {
            int o0 = 32 * s + 4 * t;
            uint32_t ah[4], al[4];
            load_afrag(ah, AH, lr, o0);
            load_afrag(al, AL, lr, o0);
            #pragma unroll
            for (int j = 0; j < 16; j++)
                mma2(acc[j], ah, al, B1, nbase + j * 8 + g, o0);
        }

        // ---- per-role nonlinearity ----
        if (isH) {
            float s1 = 0.f, q1 = 0.f, s2 = 0.f, q2 = 0.f;
            #pragma unroll
            for (int j = 0; j < 16; j++) {
                s1 += acc[j][0] + acc[j][1];
                q1 += acc[j][0] * acc[j][0] + acc[j][1] * acc[j][1];
                s2 += acc[j][2] + acc[j][3];
                q2 += acc[j][2] * acc[j][2] + acc[j][3] * acc[j][3];
            }
            #pragma unroll
            for (int o = 1; o <= 2; o <<= 1) {
                s1 += __shfl_xor_sync(0xFFFFFFFFu, s1, o);
                q1 += __shfl_xor_sync(0xFFFFFFFFu, q1, o);
                s2 += __shfl_xor_sync(0xFFFFFFFFu, s2, o);
                q2 += __shfl_xor_sync(0xFFFFFFFFu, q2, o);
            }
            float mu1 = s1 * (1.f / 128.f), rs1 = rsqrtf(q1 * (1.f / 128.f) - mu1 * mu1 + EPSC);
            float mu2 = s2 * (1.f / 128.f), rs2 = rsqrtf(q2 * (1.f / 128.f) - mu2 * mu2 + EPSC);
            #pragma unroll
            for (int j = 0; j < 16; j++) {
                int col = j * 8 + 2 * t;
                float2 gv = *(const float2*)(g1 + col);
                float2 bv = *(const float2*)(be1 + col);
                float y0 = (acc[j][0] - mu1) * rs1 * gv.x + bv.x;
                float y1 = (acc[j][1] - mu1) * rs1 * gv.y + bv.y;
                float y2 = (acc[j][2] - mu2) * rs2 * gv.x + bv.x;
                float y3 = (acc[j][3] - mu2) * rs2 * gv.y + bv.y;
                acc[j][0] = 0.5f * y0 * (1.f + erff(y0 * SQRT1_2));
                acc[j][1] = 0.5f * y1 * (1.f + erff(y1 * SQRT1_2));
                acc[j][2] = 0.5f * y2 * (1.f + erff(y2 * SQRT1_2));
                acc[j][3] = 0.5f * y3 * (1.f + erff(y3 * SQRT1_2));
            }
        } else {
            #pragma unroll
            for (int j = 0; j < 16; j++)
                #pragma unroll
                for (int c = 0; c < 4; c++)
                    acc[j][c] = 1.f / (1.f + expf(-acc[j][c]));
            // sigmoid for cols 0..63 -> G buffer (h-warp's epilogue half)
            #pragma unroll
            for (int j = 0; j < 8; j++) {
                int col = j * 8 + 2 * t;
                *(float2*)(G + gofs(lr, col))     = make_float2(acc[j][0], acc[j][1]);
                *(float2*)(G + gofs(lr + 8, col)) = make_float2(acc[j][2], acc[j][3]);
            }
        }
        PAIR_BAR(barid);   // A1 reads done; G written

        // ---- h: write A2 (gelu h) into A region ----
        if (isH) {
            #pragma unroll
            for (int j = 0; j < 16; j++) {
                uint32_t h0, l0, h1, l1;
                split_packh(acc[j][0], acc[j][1], h0, l0);
                split_packh(acc[j][2], acc[j][3], h1, l1);
                int b = 16 * j + 4 * t;
                *(uint32_t*)(AH + swb(lr, b))     = h0;
                *(uint32_t*)(AL + swb(lr, b))     = l0;
                *(uint32_t*)(AH + swb(lr + 8, b)) = h1;
                *(uint32_t*)(AL + swb(lr + 8, b)) = l1;
            }
        }
        PAIR_BAR(barid);   // A2 visible to both warps

        // ---- GEMM2 split: h computes n 0..63, gate n 64..127 ----
        const int nb2 = isH ? 0 : 64;
        float acc2[8][4];
        #pragma unroll
        for (int jl = 0; jl < 8; jl++)
            #pragma unroll
            for (int c = 0; c < 4; c++) acc2[jl][c] = 0.f;
        #pragma unroll
        for (int s = 0; s < 8; s++) {
            int o0 = 32 * s + 4 * t;
            uint32_t ah[4], al[4];
            load_afrag(ah, AH, lr, o0);
            load_afrag(al, AL, lr, o0);
            #pragma unroll
            for (int jl = 0; jl < 8; jl++)
                mma2(acc2[jl], ah, al, W2s, nb2 + jl * 8 + g, o0);
        }

        // ---- epilogue half per warp: r = (h2+b2)*gate + ea ----
        float r[8][4];
        #pragma unroll
        for (int jl = 0; jl < 8; jl++) {
            int col = nb2 + jl * 8 + 2 * t;
            float2 bv = *(const float2*)(b2 + col);
            float2 eA = *(const float2*)(ea + (size_t)e1 * 128 + col);
            float2 eB = *(const float2*)(ea + (size_t)e2 * 128 + col);
            float g0, g1v, g2, g3;
            if (isH) {
                float2 gA = *(const float2*)(G + gofs(lr, col));
                float2 gB = *(const float2*)(G + gofs(lr + 8, col));
                g0 = gA.x; g1v = gA.y; g2 = gB.x; g3 = gB.y;
            } else {
                g0 = acc[8 + jl][0]; g1v = acc[8 + jl][1];
                g2 = acc[8 + jl][2]; g3 = acc[8 + jl][3];
            }
            r[jl][0] = (acc2[jl][0] + bv.x) * g0 + eA.x;
            r[jl][1] = (acc2[jl][1] + bv.y) * g1v + eA.y;
            r[jl][2] = (acc2[jl][2] + bv.x) * g2 + eB.x;
            r[jl][3] = (acc2[jl][3] + bv.y) * g3 + eB.y;
        }

        // ---- final LN: partial sums over this warp's 64 cols, exchange ----
        float s1 = 0.f, q1 = 0.f, s2 = 0.f, q2 = 0.f;
        #pragma unroll
        for (int jl = 0; jl < 8; jl++) {
            s1 += r[jl][0] + r[jl][1];
            q1 += r[jl][0] * r[jl][0] + r[jl][1] * r[jl][1];
            s2 += r[jl][2] + r[jl][3];
            q2 += r[jl][2] * r[jl][2] + r[jl][3] * r[jl][3];
        }
        #pragma unroll
        for (int o = 1; o <= 2; o <<= 1) {
            s1 += __shfl_xor_sync(0xFFFFFFFFu, s1, o);
            q1 += __shfl_xor_sync(0xFFFFFFFFu, q1, o);
            s2 += __shfl_xor_sync(0xFFFFFFFFu, s2, o);
            q2 += __shfl_xor_sync(0xFFFFFFFFu, q2, o);
        }
        {
            float* sp = S + pw * 64 + (isH ? 0 : 32) + g * 4;
            if (t == 0) { sp[0] = s1; sp[1] = q1; sp[2] = s2; sp[3] = q2; }
        }
        PAIR_BAR(barid);
        {
            const float* sp = S + pw * 64 + (isH ? 32 : 0) + g * 4;
            s1 += sp[0]; q1 += sp[1]; s2 += sp[2]; q2 += sp[3];
        }
        float mu1 = s1 * (1.f / 128.f), rs1 = rsqrtf(q1 * (1.f / 128.f) - mu1 * mu1 + EPSC);
        float mu2 = s2 * (1.f / 128.f), rs2 = rsqrtf(q2 * (1.f / 128.f) - mu2 * mu2 + EPSC);
        #pragma unroll
        for (int jl = 0; jl < 8; jl++) {
            int col = nb2 + jl * 8 + 2 * t;
            float2 gv = *(const float2*)(gn + col);
            float2 bv = *(const float2*)(bn + col);
            float2 o1, o2;
            o1.x = (r[jl][0] - mu1) * rs1 * gv.x + bv.x;
            o1.y = (r[jl][1] - mu1) * rs1 * gv.y + bv.y;
            o2.x = (r[jl][2] - mu2) * rs2 * gv.x + bv.x;
            o2.y = (r[jl][3] - mu2) * rs2 * gv.y + bv.y;
            *(float2*)(out + (size_t)e1 * 128 + col) = o1;
            *(float2*)(out + (size_t)e2 * 128 + col) = o2;
        }
    }
}

// ---------------------------------------------------------------------------
extern "C" void kernel_launch(void* const* d_in, const int* in_sizes, int n_in,
                              void* d_out, int out_size)
{
    const float* x   = (const float*)d_in[0];
    const int*   ei  = (const int*)d_in[1];
    const float* ea  = (const float*)d_in[2];
    const float* W1  = (const float*)d_in[3];
    const float* b1  = (const float*)d_in[4];
    const float* g1  = (const float*)d_in[5];
    const float* be1 = (const float*)d_in[6];
    const float* W2  = (const float*)d_in[7];
    const float* b2  = (const float*)d_in[8];
    const float* Wg  = (const float*)d_in[9];
    const float* bg  = (const float*)d_in[10];
    const float* gn  = (const float*)d_in[11];
    const float* bn  = (const float*)d_in[12];
    float*       out = (float*)d_out;

    const int node_smem = 196608;
    const int edge_smem = 198656;
    cudaFuncSetAttribute(node_mma_kernel, cudaFuncAttributeMaxDynamicSharedMemorySize, node_smem);
    cudaFuncSetAttribute(edge_mma_kernel, cudaFuncAttributeMaxDynamicSharedMemorySize, edge_smem);

    prep_kernel<<<448, 256>>>(W1, Wg, W2);
    node_mma_kernel<<<GRID_P, 512, node_smem>>>(x);
    for (int part = 0; part < 4; part++)
        edge_mma_kernel<<<GRID_P, 512, edge_smem>>>(ei, ea, b1, g1, be1, b2, bg, gn, bn,
                                                    out, part * (EDGE_TILES / 4));
}

// round 10
// speedup vs baseline: 2.1248x; 1.1854x over previous
#include <cuda_runtime.h>
#include <cuda_fp16.h>
#include <stdint.h>
#include <math.h>

#define NN 100000
#define NE 524288
#define EPSC 1e-5f
#define EDGE_TILES 4096
#define NODE_TILES 391
#define GRID_P 148
#define SQRT1_2 0.70710678118654752440f

// g_T (fp16): [0:128]=x@W1[0:128] [128:256]=x@W1[128:256] [256:384]=x@Wg[0:128] [384:512]=x@Wg[128:256]
static __device__ __half g_T[(size_t)NN * 512];

// Pre-swizzled fp16 weight images
static __device__ char g_B1f_[65536];      // [W1e|Wge] 256n x 128k
static __device__ char g_W2f_[32768];      // W2 128n x 128k
static __device__ char g_BNf_[2][65536];   // node W1 / Wg, 256n x 128k

// ---------------- helpers ----------------
__device__ __forceinline__ int swb(int row, int b) {      // 256B rows, xor swizzle
    return row * 256 + (b ^ ((row & 7) << 4));
}
__device__ __forceinline__ int gofs(int row, int col) {   // fp32 gate buf, 256B rows
    return row * 256 + ((col * 4) ^ ((row & 7) << 5));
}
__device__ __forceinline__ uint32_t smem_u32(const void* p) {
    uint32_t a;
    asm("{ .reg .u64 t; cvta.to.shared.u64 t, %1; cvt.u32.u64 %0, t; }" : "=r"(a) : "l"(p));
    return a;
}
__device__ __forceinline__ void ldm_x4(uint32_t f[4], uint32_t addr) {
    asm volatile("ldmatrix.sync.aligned.m8n8.x4.shared.b16 {%0,%1,%2,%3}, [%4];"
                 : "=r"(f[0]), "=r"(f[1]), "=r"(f[2]), "=r"(f[3]) : "r"(addr));
}
__device__ __forceinline__ void mma16816h(float* c, uint32_t a0, uint32_t a1, uint32_t a2,
                                          uint32_t a3, uint32_t b0, uint32_t b1) {
    asm volatile("mma.sync.aligned.m16n8k16.row.col.f32.f16.f16.f32 "
                 "{%0,%1,%2,%3}, {%4,%5,%6,%7}, {%8,%9}, {%0,%1,%2,%3};"
                 : "+f"(c[0]), "+f"(c[1]), "+f"(c[2]), "+f"(c[3])
                 : "r"(a0), "r"(a1), "r"(a2), "r"(a3), "r"(b0), "r"(b1));
}
// manual B frag load (node kernel)
__device__ __forceinline__ void mma1(float* acc, const uint32_t a[4],
                                     const char* B, int n, int o0) {
    uint32_t b0 = *(const uint32_t*)(B + swb(n, o0));
    uint32_t b1 = *(const uint32_t*)(B + swb(n, o0 + 16));
    mma16816h(acc, a[0], a[1], a[2], a[3], b0, b1);
}
__device__ __forceinline__ void load_afrag(uint32_t f[4], const char* base, int lr, int o0) {
    f[0] = *(const uint32_t*)(base + swb(lr, o0));
    f[1] = *(const uint32_t*)(base + swb(lr + 8, o0));
    f[2] = *(const uint32_t*)(base + swb(lr, o0 + 16));
    f[3] = *(const uint32_t*)(base + swb(lr + 8, o0 + 16));
}
#define PAIR_BAR(id) asm volatile("bar.sync %0, 64;" :: "r"(id) : "memory")

// ============================================================================
// Prep kernel: build swizzled fp16 weight images.
// ============================================================================
__global__ void prep_kernel(const float* __restrict__ W1,
                            const float* __restrict__ Wg,
                            const float* __restrict__ W2)
{
    int i = blockIdx.x * 256 + threadIdx.x;
    float v;
    char* dst;
    int o;
    if (i < 32768) {
        int n = i >> 7, k = i & 127;
        v = (n < 128) ? W1[(size_t)(256 + k) * 128 + n]
                      : Wg[(size_t)(256 + k) * 128 + (n - 128)];
        o = swb(n, 2 * k); dst = g_B1f_;
    } else if (i < 49152) {
        int j = i - 32768;
        int n = j >> 7, k = j & 127;
        v = W2[(size_t)k * 128 + n];
        o = swb(n, 2 * k); dst = g_W2f_;
    } else {
        int j = i - 49152;
        int q = j >> 15; j &= 32767;
        int n = j >> 7, k = j & 127;
        const float* W = q ? Wg : W1;
        v = (n < 128) ? W[(size_t)k * 128 + n]
                      : W[(size_t)(128 + k) * 128 + (n - 128)];
        o = swb(n, 2 * k); dst = g_BNf_[q];
    }
    *(__half*)(dst + o) = __float2half_rn(v);
}

// ============================================================================
// Node kernel: 512 threads, 256-node tiles, fp16 A (single), fp16 g_T out.
// smem: B 64K | AH 64K = 131072
// ============================================================================
__global__ __launch_bounds__(512, 1)
void node_mma_kernel(const float* __restrict__ x)
{
    extern __shared__ char sm[];
    char* B  = sm;
    char* AH = sm + 65536;

    const int tid = threadIdx.x;
    const int w = tid >> 5, lane = tid & 31;
    const int g = lane >> 2, t = lane & 3;
    const int lr = w * 16 + g;

    for (int q = 0; q < 2; q++) {
        __syncthreads();
        for (int i = tid; i < 4096; i += 512)
            ((float4*)B)[i] = ((const float4*)g_BNf_[q])[i];
        __syncthreads();

        for (int tile = blockIdx.x; tile < NODE_TILES; tile += gridDim.x) {
            #pragma unroll
            for (int i = 0; i < 16; i++) {
                int r = w * 16 + i;
                int node = tile * 256 + r;
                float4 v = (node < NN) ? *(const float4*)(x + (size_t)node * 128 + lane * 4)
                                       : make_float4(0.f, 0.f, 0.f, 0.f);
                __half2 h0 = __floats2half2_rn(v.x, v.y);
                __half2 h1 = __floats2half2_rn(v.z, v.w);
                *(uint2*)(AH + swb(r, 8 * lane)) =
                    make_uint2(*(uint32_t*)&h0, *(uint32_t*)&h1);
            }
            __syncwarp();

            const int n1 = tile * 256 + lr;
            const int n2 = n1 + 8;
            #pragma unroll
            for (int nh = 0; nh < 2; nh++) {
                float acc[16][4];
                #pragma unroll
                for (int j = 0; j < 16; j++)
                    #pragma unroll
                    for (int c = 0; c < 4; c++) acc[j][c] = 0.f;
                #pragma unroll
                for (int s = 0; s < 8; s++) {
                    int o0 = 32 * s + 4 * t;
                    uint32_t a[4];
                    load_afrag(a, AH, lr, o0);
                    #pragma unroll
                    for (int j = 0; j < 16; j++)
                        mma1(acc[j], a, B, nh * 128 + j * 8 + g, o0);
                }
                __half* p1 = g_T + (size_t)n1 * 512 + q * 256 + nh * 128;
                __half* p2 = g_T + (size_t)n2 * 512 + q * 256 + nh * 128;
                #pragma unroll
                for (int j = 0; j < 16; j++) {
                    int col = j * 8 + 2 * t;
                    if (n1 < NN) *(__half2*)(p1 + col) = __floats2half2_rn(acc[j][0], acc[j][1]);
                    if (n2 < NN) *(__half2*)(p2 + col) = __floats2half2_rn(acc[j][2], acc[j][3]);
                }
            }
            __syncwarp();
        }
    }
}

// ============================================================================
// Edge kernel: 512 threads = 8 pairs {h-warp w, gate-warp w+8}, 16 edges/pair.
// fp16 A (single term), ldmatrix.x4 fragment loads, GEMM2+epilogue pair-split.
// smem: B1 64K | W2 32K | AH 32K | G 32K | S 2K = 165888
// ============================================================================
__global__ __launch_bounds__(512, 1)
void edge_mma_kernel(const int* __restrict__ ei, const float* __restrict__ ea,
                     const float* __restrict__ b1, const float* __restrict__ g1,
                     const float* __restrict__ be1, const float* __restrict__ b2,
                     const float* __restrict__ bg, const float* __restrict__ gn,
                     const float* __restrict__ bn, float* __restrict__ out,
                     int tile0)
{
    extern __shared__ char sm[];
    char* B1  = sm;
    char* W2s = sm + 65536;
    char* AH  = sm + 98304;
    char* G   = sm + 131072;
    float* S  = (float*)(sm + 163840);

    const int tid = threadIdx.x;
    const int w = tid >> 5, lane = tid & 31;
    const int g = lane >> 2, t = lane & 3;
    const int pw = w & 7;
    const bool isH = (w < 8);
    const int lr = pw * 16 + g;
    const int barid = 1 + pw;

    // ldmatrix per-lane constants (row&7 == rr in every slot)
    const int mid = lane >> 3, rr = lane & 7;
    const int aRowOff = (mid & 1) * 8 + rr;   // A: m0 rows lo, m1 rows hi, m2/m3 = k-high halves
    const int aHs = (mid >> 1) * 16;
    const int bNoff = (mid >> 1) * 8 + rr;    // B: m0/m1 = j-even (b0,b1), m2/m3 = j-odd
    const int bHs = (mid & 1) * 16;
    const uint32_t rx = (uint32_t)(rr << 4);

    const uint32_t B1u = smem_u32(B1);
    const uint32_t W2u = smem_u32(W2s);
    const uint32_t aBase = smem_u32(AH) + (uint32_t)(pw * 16 + aRowOff) * 256;

    for (int i = tid; i < 4096; i += 512) ((float4*)B1)[i] = ((const float4*)g_B1f_)[i];
    for (int i = tid; i < 2048; i += 512) ((float4*)W2s)[i] = ((const float4*)g_W2f_)[i];
    __syncthreads();

    const int tile_end = tile0 + EDGE_TILES / 4;
    for (int tile = tile0 + blockIdx.x; tile < tile_end; tile += gridDim.x) {
        // ---- indices early (resolve gather addresses during staging) ----
        const int e1 = tile * 128 + lr;
        const int e2 = e1 + 8;
        const int is1 = ei[e1], id1 = ei[NE + e1];
        const int is2 = ei[e2], id2 = ei[NE + e2];

        // ---- stage A1 (fp16): h stages rows pw*16..+7, gate +8..+15 ----
        #pragma unroll
        for (int i = 0; i < 8; i++) {
            int r = pw * 16 + (isH ? i : 8 + i);
            float4 v = *(const float4*)(ea + (size_t)(tile * 128 + r) * 128 + lane * 4);
            __half2 h0 = __floats2half2_rn(v.x, v.y);
            __half2 h1 = __floats2half2_rn(v.z, v.w);
            *(uint2*)(AH + swb(r, 8 * lane)) =
                make_uint2(*(uint32_t*)&h0, *(uint32_t*)&h1);
        }
        PAIR_BAR(barid);

        // ---- gathers (fp16 g_T) + bias ----
        const int offs = isH ? 0 : 256;
        const int offd = isH ? 128 : 384;
        const __half* T1s = g_T + (size_t)is1 * 512 + offs;
        const __half* T1d = g_T + (size_t)id1 * 512 + offd;
        const __half* T2s = g_T + (size_t)is2 * 512 + offs;
        const __half* T2d = g_T + (size_t)id2 * 512 + offd;
        const float* bias = isH ? b1 : bg;

        float acc[16][4];
        #pragma unroll
        for (int j = 0; j < 16; j++) {
            int col = j * 8 + 2 * t;
            float2 bb = *(const float2*)(bias + col);
            float2 p1 = __half22float2(*(const __half2*)(T1s + col));
            float2 q1 = __half22float2(*(const __half2*)(T1d + col));
            float2 p2 = __half22float2(*(const __half2*)(T2s + col));
            float2 q2 = __half22float2(*(const __half2*)(T2d + col));
            acc[j][0] = bb.x + p1.x + q1.x;  acc[j][1] = bb.y + p1.y + q1.y;
            acc[j][2] = bb.x + p2.x + q2.x;  acc[j][3] = bb.y + p2.y + q2.y;
        }

        // ---- GEMM1 via ldmatrix ----
        const int nbase = isH ? 0 : 128;
        #pragma unroll
        for (int s = 0; s < 8; s++) {
            uint32_t a[4];
            ldm_x4(a, aBase + (((uint32_t)(32 * s + aHs)) ^ rx));
            #pragma unroll
            for (int jp = 0; jp < 8; jp++) {
                uint32_t b[4];
                int n = nbase + jp * 16 + bNoff;
                ldm_x4(b, B1u + (uint32_t)n * 256 + (((uint32_t)(32 * s + bHs)) ^ rx));
                mma16816h(acc[2 * jp],     a[0], a[1], a[2], a[3], b[0], b[1]);
                mma16816h(acc[2 * jp + 1], a[0], a[1], a[2], a[3], b[2], b[3]);
            }
        }

        // ---- per-role nonlinearity ----
        if (isH) {
            float s1 = 0.f, q1 = 0.f, s2 = 0.f, q2 = 0.f;
            #pragma unroll
            for (int j = 0; j < 16; j++) {
                s1 += acc[j][0] + acc[j][1];
                q1 += acc[j][0] * acc[j][0] + acc[j][1] * acc[j][1];
                s2 += acc[j][2] + acc[j][3];
                q2 += acc[j][2] * acc[j][2] + acc[j][3] * acc[j][3];
            }
            #pragma unroll
            for (int o = 1; o <= 2; o <<= 1) {
                s1 += __shfl_xor_sync(0xFFFFFFFFu, s1, o);
                q1 += __shfl_xor_sync(0xFFFFFFFFu, q1, o);
                s2 += __shfl_xor_sync(0xFFFFFFFFu, s2, o);
                q2 += __shfl_xor_sync(0xFFFFFFFFu, q2, o);
            }
            float mu1 = s1 * (1.f / 128.f), rs1 = rsqrtf(q1 * (1.f / 128.f) - mu1 * mu1 + EPSC);
            float mu2 = s2 * (1.f / 128.f), rs2 = rsqrtf(q2 * (1.f / 128.f) - mu2 * mu2 + EPSC);
            #pragma unroll
            for (int j = 0; j < 16; j++) {
                int col = j * 8 + 2 * t;
                float2 gv = *(const float2*)(g1 + col);
                float2 bv = *(const float2*)(be1 + col);
                float y0 = (acc[j][0] - mu1) * rs1 * gv.x + bv.x;
                float y1 = (acc[j][1] - mu1) * rs1 * gv.y + bv.y;
                float y2 = (acc[j][2] - mu2) * rs2 * gv.x + bv.x;
                float y3 = (acc[j][3] - mu2) * rs2 * gv.y + bv.y;
                acc[j][0] = 0.5f * y0 * (1.f + erff(y0 * SQRT1_2));
                acc[j][1] = 0.5f * y1 * (1.f + erff(y1 * SQRT1_2));
                acc[j][2] = 0.5f * y2 * (1.f + erff(y2 * SQRT1_2));
                acc[j][3] = 0.5f * y3 * (1.f + erff(y3 * SQRT1_2));
            }
        } else {
            #pragma unroll
            for (int j = 0; j < 16; j++)
                #pragma unroll
                for (int c = 0; c < 4; c++)
                    acc[j][c] = 1.f / (1.f + expf(-acc[j][c]));
            #pragma unroll
            for (int j = 0; j < 8; j++) {        // sigmoid cols 0..63 -> G
                int col = j * 8 + 2 * t;
                *(float2*)(G + gofs(lr, col))     = make_float2(acc[j][0], acc[j][1]);
                *(float2*)(G + gofs(lr + 8, col)) = make_float2(acc[j][2], acc[j][3]);
            }
        }
        PAIR_BAR(barid);   // A1 reads done; G written

        if (isH) {         // write A2 = gelu(h) fp16
            #pragma unroll
            for (int j = 0; j < 16; j++) {
                __half2 p0 = __floats2half2_rn(acc[j][0], acc[j][1]);
                __half2 p1 = __floats2half2_rn(acc[j][2], acc[j][3]);
                int b = 16 * j + 4 * t;
                *(uint32_t*)(AH + swb(lr, b))     = *(uint32_t*)&p0;
                *(uint32_t*)(AH + swb(lr + 8, b)) = *(uint32_t*)&p1;
            }
        }
        PAIR_BAR(barid);   // A2 visible

        // ---- GEMM2 split: h -> n 0..63, gate -> n 64..127 ----
        const int nb2 = isH ? 0 : 64;
        float acc2[8][4];
        #pragma unroll
        for (int jl = 0; jl < 8; jl++)
            #pragma unroll
            for (int c = 0; c < 4; c++) acc2[jl][c] = 0.f;
        #pragma unroll
        for (int s = 0; s < 8; s++) {
            uint32_t a[4];
            ldm_x4(a, aBase + (((uint32_t)(32 * s + aHs)) ^ rx));
            #pragma unroll
            for (int jp = 0; jp < 4; jp++) {
                uint32_t b[4];
                int n = nb2 + jp * 16 + bNoff;
                ldm_x4(b, W2u + (uint32_t)n * 256 + (((uint32_t)(32 * s + bHs)) ^ rx));
                mma16816h(acc2[2 * jp],     a[0], a[1], a[2], a[3], b[0], b[1]);
                mma16816h(acc2[2 * jp + 1], a[0], a[1], a[2], a[3], b[2], b[3]);
            }
        }

        // ---- epilogue half per warp: r = (h2+b2)*gate + ea ----
        float r[8][4];
        #pragma unroll
        for (int jl = 0; jl < 8; jl++) {
            int col = nb2 + jl * 8 + 2 * t;
            float2 bv = *(const float2*)(b2 + col);
            float2 eA = *(const float2*)(ea + (size_t)e1 * 128 + col);
            float2 eB = *(const float2*)(ea + (size_t)e2 * 128 + col);
            float g0, g1v, g2, g3;
            if (isH) {
                float2 gA = *(const float2*)(G + gofs(lr, col));
                float2 gB = *(const float2*)(G + gofs(lr + 8, col));
                g0 = gA.x; g1v = gA.y; g2 = gB.x; g3 = gB.y;
            } else {
                g0 = acc[8 + jl][0]; g1v = acc[8 + jl][1];
                g2 = acc[8 + jl][2]; g3 = acc[8 + jl][3];
            }
            r[jl][0] = (acc2[jl][0] + bv.x) * g0 + eA.x;
            r[jl][1] = (acc2[jl][1] + bv.y) * g1v + eA.y;
            r[jl][2] = (acc2[jl][2] + bv.x) * g2 + eB.x;
            r[jl][3] = (acc2[jl][3] + bv.y) * g3 + eB.y;
        }

        // ---- final LN: partial sums + pair exchange ----
        float s1 = 0.f, q1 = 0.f, s2 = 0.f, q2 = 0.f;
        #pragma unroll
        for (int jl = 0; jl < 8; jl++) {
            s1 += r[jl][0] + r[jl][1];
            q1 += r[jl][0] * r[jl][0] + r[jl][1] * r[jl][1];
            s2 += r[jl][2] + r[jl][3];
            q2 += r[jl][2] * r[jl][2] + r[jl][3] * r[jl][3];
        }
        #pragma unroll
        for (int o = 1; o <= 2; o <<= 1) {
            s1 += __shfl_xor_sync(0xFFFFFFFFu, s1, o);
            q1 += __shfl_xor_sync(0xFFFFFFFFu, q1, o);
            s2 += __shfl_xor_sync(0xFFFFFFFFu, s2, o);
            q2 += __shfl_xor_sync(0xFFFFFFFFu, q2, o);
        }
        {
            float* sp = S + pw * 64 + (isH ? 0 : 32) + g * 4;
            if (t == 0) { sp[0] = s1; sp[1] = q1; sp[2] = s2; sp[3] = q2; }
        }
        PAIR_BAR(barid);
        {
            const float* sp = S + pw * 64 + (isH ? 32 : 0) + g * 4;
            s1 += sp[0]; q1 += sp[1]; s2 += sp[2]; q2 += sp[3];
        }
        float mu1 = s1 * (1.f / 128.f), rs1 = rsqrtf(q1 * (1.f / 128.f) - mu1 * mu1 + EPSC);
        float mu2 = s2 * (1.f / 128.f), rs2 = rsqrtf(q2 * (1.f / 128.f) - mu2 * mu2 + EPSC);
        #pragma unroll
        for (int jl = 0; jl < 8; jl++) {
            int col = nb2 + jl * 8 + 2 * t;
            float2 gv = *(const float2*)(gn + col);
            float2 bv = *(const float2*)(bn + col);
            float2 o1, o2;
            o1.x = (r[jl][0] - mu1) * rs1 * gv.x + bv.x;
            o1.y = (r[jl][1] - mu1) * rs1 * gv.y + bv.y;
            o2.x = (r[jl][2] - mu2) * rs2 * gv.x + bv.x;
            o2.y = (r[jl][3] - mu2) * rs2 * gv.y + bv.y;
            *(float2*)(out + (size_t)e1 * 128 + col) = o1;
            *(float2*)(out + (size_t)e2 * 128 + col) = o2;
        }
    }
}

// ---------------------------------------------------------------------------
extern "C" void kernel_launch(void* const* d_in, const int* in_sizes, int n_in,
                              void* d_out, int out_size)
{
    const float* x   = (const float*)d_in[0];
    const int*   ei  = (const int*)d_in[1];
    const float* ea  = (const float*)d_in[2];
    const float* W1  = (const float*)d_in[3];
    const float* b1  = (const float*)d_in[4];
    const float* g1  = (const float*)d_in[5];
    const float* be1 = (const float*)d_in[6];
    const float* W2  = (const float*)d_in[7];
    const float* b2  = (const float*)d_in[8];
    const float* Wg  = (const float*)d_in[9];
    const float* bg  = (const float*)d_in[10];
    const float* gn  = (const float*)d_in[11];
    const float* bn  = (const float*)d_in[12];
    float*       out = (float*)d_out;

    const int node_smem = 131072;
    const int edge_smem = 165888;
    cudaFuncSetAttribute(node_mma_kernel, cudaFuncAttributeMaxDynamicSharedMemorySize, node_smem);
    cudaFuncSetAttribute(edge_mma_kernel, cudaFuncAttributeMaxDynamicSharedMemorySize, edge_smem);

    prep_kernel<<<448, 256>>>(W1, Wg, W2);
    node_mma_kernel<<<GRID_P, 512, node_smem>>>(x);
    for (int part = 0; part < 4; part++)
        edge_mma_kernel<<<GRID_P, 512, edge_smem>>>(ei, ea, b1, g1, be1, b2, bg, gn, bn,
                                                    out, part * (EDGE_TILES / 4));
}